// round 1
// baseline (speedup 1.0000x reference)
#include <cuda_runtime.h>

#define MROWS 64000
#define MAXD  160
#define NCHUNK 64
#define CHUNK 1000

// ---------------- scratch (device globals: no allocation allowed) ----------------
__device__ float g_atlas0[MROWS * MAXD];
__device__ float g_atlas1[MROWS * MAXD];
__device__ float g_B    [MROWS * MAXD];
__device__ float g_q    [MROWS * MAXD];
__device__ float g_k    [MROWS * MAXD];
__device__ float g_v    [MROWS * MAXD];
__device__ float g_cross[MROWS * MAXD];
__device__ float g_Spart[NCHUNK * MAXD * MAXD];
__device__ float g_S    [MAXD * MAXD];
__device__ float g_attnT[MAXD * MAXD];

// ---------------- pad + unfold: feat -> (64000, d) ----------------
// m = c*1000 + i0*100 + i1*10 + i2 ; s = (z0*w1 + z1)*w2 + z2
// padded voxel p_k = i_k*w_k + z_k ; source voxel = p_k - pb_k (zero if OOB)
__global__ __launch_bounds__(256) void unfold_kernel(
    const float* __restrict__ src, float* __restrict__ dst, int d,
    int D0, int D1, int D2, long s0, long s1, long s2, long sc,
    int w0, int w1, int w2, int pb0, int pb1, int pb2)
{
    long idx = (long)blockIdx.x * blockDim.x + threadIdx.x;
    long total = (long)MROWS * d;
    if (idx >= total) return;
    int  s = (int)(idx % d);
    long m = idx / d;
    int c = (int)(m / 1000);
    int r = (int)(m % 1000);
    int i0 = r / 100, i1 = (r / 10) % 10, i2 = r % 10;
    int z2 = s % w2; int t = s / w2; int z1 = t % w1; int z0 = t / w1;
    int p0 = i0 * w0 + z0 - pb0;
    int p1 = i1 * w1 + z1 - pb1;
    int p2 = i2 * w2 + z2 - pb2;
    float v = 0.f;
    if ((unsigned)p0 < (unsigned)D0 && (unsigned)p1 < (unsigned)D1 && (unsigned)p2 < (unsigned)D2)
        v = src[(long)c * sc + (long)p0 * s0 + (long)p1 * s1 + (long)p2 * s2];
    dst[idx] = v;
}

// ---------------- fold: (64000, d) -> output tensor (with crop + strides) ----------------
__global__ __launch_bounds__(256) void fold_kernel(
    const float* __restrict__ cross, float* __restrict__ out, int d,
    int D0, int D1, int D2, long s0, long s1, long s2, long sc,
    int w0, int w1, int w2, int pb0, int pb1, int pb2)
{
    long idx = (long)blockIdx.x * blockDim.x + threadIdx.x;
    long total = 64L * D0 * D1 * D2;
    if (idx >= total) return;
    int x2 = (int)(idx % D2); long t = idx / D2;
    int x1 = (int)(t % D1);  t /= D1;
    int x0 = (int)(t % D0);
    int c  = (int)(t / D0);
    int p0 = x0 + pb0, p1 = x1 + pb1, p2 = x2 + pb2;
    int i0 = p0 / w0, z0 = p0 - i0 * w0;
    int i1 = p1 / w1, z1 = p1 - i1 * w1;
    int i2 = p2 / w2, z2 = p2 - i2 * w2;
    long m = (long)c * 1000 + i0 * 100 + i1 * 10 + i2;
    int  s = (z0 * w1 + z1) * w2 + z2;
    out[(long)c * sc + (long)x0 * s0 + (long)x1 * s1 + (long)x2 * s2] = cross[m * d + s];
}

// ---------------- nearest3d resample of atlas cube (64000, dp) -> (64000, dn) ----------------
__global__ __launch_bounds__(256) void resample_kernel(
    const float* __restrict__ src, float* __restrict__ dst,
    int wp0, int wp1, int wp2, int wn0, int wn1, int wn2)
{
    int dp = wp0 * wp1 * wp2, dn = wn0 * wn1 * wn2;
    long idx = (long)blockIdx.x * blockDim.x + threadIdx.x;
    long total = (long)MROWS * dn;
    if (idx >= total) return;
    int  s = (int)(idx % dn);
    long m = idx / dn;
    int z2 = s % wn2; int t = s / wn2; int z1 = t % wn1; int z0 = t / wn1;
    int o0 = (z0 * wp0) / wn0;   // exact floor(z*d/od) for positive ints
    int o1 = (z1 * wp1) / wn1;
    int o2 = (z2 * wp2) / wn2;
    dst[idx] = src[m * dp + (o0 * wp1 + o1) * wp2 + o2];
}

// ---------------- fp32 SGEMM  C[M,N] = A[M,K] @ W[K,N] (+ bias) ----------------
// BM=128, BN=64, BK=16, 256 threads, 8x4 microtile.  M must be a multiple of 128.
#define BM 128
#define BN 64
#define BKK 16
__global__ __launch_bounds__(256) void sgemm_bias(
    const float* __restrict__ A, const float* __restrict__ W,
    const float* __restrict__ bias, float* __restrict__ C,
    int M, int K, int N)
{
    __shared__ float As[BKK][BM + 1];
    __shared__ float Ws[BKK][BN];
    const int bm = blockIdx.x * BM;
    const int bn = blockIdx.y * BN;
    const int tid = threadIdx.x;
    const int tx = tid & 15;   // 16 col-groups of 4
    const int ty = tid >> 4;   // 16 row-groups of 8
    float acc[8][4];
#pragma unroll
    for (int i = 0; i < 8; i++)
#pragma unroll
        for (int j = 0; j < 4; j++) acc[i][j] = 0.f;

    for (int k0 = 0; k0 < K; k0 += BKK) {
#pragma unroll
        for (int i = 0; i < 8; i++) {            // A tile 128x16
            int l = i * 256 + tid;
            int row = l >> 4;
            int kk  = l & 15;
            int gk = k0 + kk;
            As[kk][row] = (gk < K) ? A[(long)(bm + row) * K + gk] : 0.f;
        }
#pragma unroll
        for (int i = 0; i < 4; i++) {            // W tile 16x64
            int l = i * 256 + tid;
            int kk  = l >> 6;
            int col = l & 63;
            int gk = k0 + kk, gn = bn + col;
            Ws[kk][col] = (gk < K && gn < N) ? W[(long)gk * N + gn] : 0.f;
        }
        __syncthreads();
#pragma unroll
        for (int kk = 0; kk < BKK; kk++) {
            float ra[8], rw[4];
#pragma unroll
            for (int i = 0; i < 8; i++) ra[i] = As[kk][ty * 8 + i];
#pragma unroll
            for (int j = 0; j < 4; j++) rw[j] = Ws[kk][tx * 4 + j];
#pragma unroll
            for (int i = 0; i < 8; i++)
#pragma unroll
                for (int j = 0; j < 4; j++) acc[i][j] += ra[i] * rw[j];
        }
        __syncthreads();
    }
#pragma unroll
    for (int i = 0; i < 8; i++) {
        int m = bm + ty * 8 + i;
#pragma unroll
        for (int j = 0; j < 4; j++) {
            int n = bn + tx * 4 + j;
            if (n < N) {
                float v = acc[i][j];
                if (bias) v += bias[n];
                C[(long)m * N + n] = v;
            }
        }
    }
}

// ---------------- S partials:  Spart[cz][i][j] = sum_{m in chunk cz} q[m,i]*k[m,j] ----------------
#define SB 64
#define SMB 16
__global__ __launch_bounds__(256) void spart_kernel(
    const float* __restrict__ q, const float* __restrict__ k,
    float* __restrict__ Sp, int N)
{
    __shared__ float Qs[SMB][SB];
    __shared__ float Ks[SMB][SB];
    const int i0 = blockIdx.x * SB;
    const int j0 = blockIdx.y * SB;
    const int cz = blockIdx.z;
    const int m0 = cz * CHUNK;
    const int m1 = m0 + CHUNK;   // MROWS = NCHUNK*CHUNK exactly
    const int tid = threadIdx.x;
    const int tx = tid & 15;
    const int ty = tid >> 4;
    float acc[4][4];
#pragma unroll
    for (int i = 0; i < 4; i++)
#pragma unroll
        for (int j = 0; j < 4; j++) acc[i][j] = 0.f;

    for (int m = m0; m < m1; m += SMB) {
#pragma unroll
        for (int i = 0; i < 4; i++) {
            int l = i * 256 + tid;
            int mm = l >> 6;       // /64
            int col = l & 63;
            int gm = m + mm;
            int gi = i0 + col, gj = j0 + col;
            Qs[mm][col] = (gm < m1 && gi < N) ? q[(long)gm * N + gi] : 0.f;
            Ks[mm][col] = (gm < m1 && gj < N) ? k[(long)gm * N + gj] : 0.f;
        }
        __syncthreads();
#pragma unroll
        for (int mm = 0; mm < SMB; mm++) {
            float rq[4], rk[4];
#pragma unroll
            for (int i = 0; i < 4; i++) rq[i] = Qs[mm][ty * 4 + i];
#pragma unroll
            for (int j = 0; j < 4; j++) rk[j] = Ks[mm][tx * 4 + j];
#pragma unroll
            for (int i = 0; i < 4; i++)
#pragma unroll
                for (int j = 0; j < 4; j++) acc[i][j] += rq[i] * rk[j];
        }
        __syncthreads();
    }
#pragma unroll
    for (int i = 0; i < 4; i++) {
        int gi = i0 + ty * 4 + i;
#pragma unroll
        for (int j = 0; j < 4; j++) {
            int gj = j0 + tx * 4 + j;
            if (gi < N && gj < N)
                Sp[(long)cz * N * N + (long)gi * N + gj] = acc[i][j];
        }
    }
}

__global__ __launch_bounds__(256) void sreduce_kernel(
    const float* __restrict__ Sp, float* __restrict__ S, int NN)
{
    int idx = blockIdx.x * blockDim.x + threadIdx.x;
    if (idx >= NN) return;
    float s = 0.f;
#pragma unroll 4
    for (int c = 0; c < NCHUNK; c++) s += Sp[(long)c * NN + idx];
    S[idx] = s;
}

// softmax over j of S[i,:], written TRANSPOSED: attnT[j,i] so cross is a plain GEMM
__global__ __launch_bounds__(256) void softmaxT_kernel(
    const float* __restrict__ S, float* __restrict__ attnT, int N)
{
    __shared__ float red[256];
    const int i = blockIdx.x;
    const int tid = threadIdx.x;
    float v = (tid < N) ? S[(long)i * N + tid] : -3.4e38f;
    red[tid] = v; __syncthreads();
    for (int off = 128; off > 0; off >>= 1) {
        if (tid < off) red[tid] = fmaxf(red[tid], red[tid + off]);
        __syncthreads();
    }
    float mx = red[0]; __syncthreads();
    float e = (tid < N) ? expf(v - mx) : 0.f;
    red[tid] = e; __syncthreads();
    for (int off = 128; off > 0; off >>= 1) {
        if (tid < off) red[tid] += red[tid + off];
        __syncthreads();
    }
    float sum = red[0];
    if (tid < N) attnT[(long)tid * N + i] = e / sum;
}

// ---------------- driver ----------------
struct BranchDesc {
    int D0, D1, D2;          // effective (post-transpose) spatial dims
    long s0, s1, s2, sc;     // element strides into the real in/out arrays
    int w0, w1, w2;          // cube grid dims (d = w0*w1*w2)
    int pb0, pb1, pb2;       // pad-before
    long outOff;             // offset into d_out
    int wi;                  // d_in index of Wq
};

extern "C" void kernel_launch(void* const* d_in, const int* in_sizes, int n_in,
                              void* d_out, int out_size)
{
    const float* axi   = (const float*)d_in[0];
    const float* cor   = (const float*)d_in[1];
    const float* sag   = (const float*)d_in[2];
    const float* atlas = (const float*)d_in[3];
    float* out = (float*)d_out;

    float *A0, *A1, *B, *Q, *Kb, *V, *Cr, *Sp, *S, *AT;
    cudaGetSymbolAddress((void**)&A0, g_atlas0);
    cudaGetSymbolAddress((void**)&A1, g_atlas1);
    cudaGetSymbolAddress((void**)&B,  g_B);
    cudaGetSymbolAddress((void**)&Q,  g_q);
    cudaGetSymbolAddress((void**)&Kb, g_k);
    cudaGetSymbolAddress((void**)&V,  g_v);
    cudaGetSymbolAddress((void**)&Cr, g_cross);
    cudaGetSymbolAddress((void**)&Sp, g_Spart);
    cudaGetSymbolAddress((void**)&S,  g_S);
    cudaGetSymbolAddress((void**)&AT, g_attnT);

    // atlas_feat (64,46,56,38): ps=(50,60,40), w=(5,6,4), pads=(4,4,2) -> pb=(2,2,1)
    {
        long total = (long)MROWS * 120;
        unfold_kernel<<<(unsigned)((total + 255) / 256), 256>>>(
            atlas, A0, 120, 46, 56, 38, 2128, 38, 1, 97888, 5, 6, 4, 2, 2, 1);
    }

    // axi: (48,66,38) natural.             cor eff (a,b,e)=(38,38,66) from cor[c,a,e,b].
    // sag eff (a,b,e)=(38,78,48) from sag[c,e,b,a].  In/out strides coincide per branch.
    BranchDesc br[3] = {
        { 48, 66, 38, 2508, 38,   1, 120384, 5, 7, 4, 1, 2, 1, 0L,        4 },
        { 38, 38, 66, 2508,  1,  38,  95304, 4, 4, 7, 1, 1, 2, 7704576L, 10 },
        { 38, 78, 48,    1, 38, 2964, 142272, 4, 8, 5, 1, 1, 1, 13804032L, 16 },
    };

    float* Aprev = A0;
    float* Acur  = A1;
    int wp0 = 5, wp1 = 6, wp2 = 4;

    for (int b = 0; b < 3; b++) {
        const BranchDesc& r = br[b];
        const int d = r.w0 * r.w1 * r.w2;
        const float* Wq = (const float*)d_in[r.wi + 0];
        const float* bq = (const float*)d_in[r.wi + 1];
        const float* Wk = (const float*)d_in[r.wi + 2];
        const float* bk = (const float*)d_in[r.wi + 3];
        const float* Wv = (const float*)d_in[r.wi + 4];
        const float* bv = (const float*)d_in[r.wi + 5];

        // 1) resample atlas cube to this branch's grid -> A (= q input)
        {
            long total = (long)MROWS * d;
            resample_kernel<<<(unsigned)((total + 255) / 256), 256>>>(
                Aprev, Acur, wp0, wp1, wp2, r.w0, r.w1, r.w2);
        }
        // 2) unfold feature volume -> B
        {
            long total = (long)MROWS * d;
            unfold_kernel<<<(unsigned)((total + 255) / 256), 256>>>(
                r.outOff == 0 ? axi : (b == 1 ? cor : sag), B, d,
                r.D0, r.D1, r.D2, r.s0, r.s1, r.s2, r.sc,
                r.w0, r.w1, r.w2, r.pb0, r.pb1, r.pb2);
        }
        // 3) q/k/v GEMMs
        dim3 gg(MROWS / BM, (d + BN - 1) / BN);
        sgemm_bias<<<gg, 256>>>(Acur, Wq, bq, Q,  MROWS, d, d);
        sgemm_bias<<<gg, 256>>>(B,    Wk, bk, Kb, MROWS, d, d);
        sgemm_bias<<<gg, 256>>>(B,    Wv, bv, V,  MROWS, d, d);
        // 4) S = q^T k (split-M partials, deterministic), softmax -> attnT
        int tI = (d + SB - 1) / SB;
        dim3 gs(tI, tI, NCHUNK);
        spart_kernel<<<gs, 256>>>(Q, Kb, Sp, d);
        sreduce_kernel<<<(d * d + 255) / 256, 256>>>(Sp, S, d * d);
        softmaxT_kernel<<<d, 256>>>(S, AT, d);
        // 5) cross = v @ attnT
        sgemm_bias<<<gg, 256>>>(V, AT, (const float*)nullptr, Cr, MROWS, d, d);
        // 6) fold + crop into output slot
        {
            long total = 64L * r.D0 * r.D1 * r.D2;
            fold_kernel<<<(unsigned)((total + 255) / 256), 256>>>(
                Cr, out + r.outOff, d,
                r.D0, r.D1, r.D2, r.s0, r.s1, r.s2, r.sc,
                r.w0, r.w1, r.w2, r.pb0, r.pb1, r.pb2);
        }
        // chain atlas cube
        float* t = Aprev; Aprev = Acur; Acur = t;
        wp0 = r.w0; wp1 = r.w1; wp2 = r.w2;
    }
}